// round 2
// baseline (speedup 1.0000x reference)
#include <cuda_runtime.h>

#define NP 100000
#define KN 16
#define NK (NP*KN)

// ---------------- device scratch ----------------
__device__ int   g_cnt[NP];
__device__ float g_g1[NP*64];          // f-path layer1 pre-BN, later reused as fpost
__device__ float g_g2[NP*64];          // f-path layer2 pre-BN
__device__ float g_y1w[NK*8];
__device__ float g_y2w[NK*8];
__device__ float g_new[NP*1024];       // new_flat (N, H*MID)
__device__ float g_z[NP*64];
__device__ float g_stats[448];
__device__ float g_ss[448];

#define F1_OFF 0
#define W1_OFF 128
#define F2_OFF 144
#define W2_OFF 272
#define W3_OFF 288
#define Z_OFF  320

#define EPS_BN 1e-5f

// ---------------- init ----------------
__global__ void k_zero() {
    int i = blockIdx.x * 256 + threadIdx.x;
    if (i < NP)  g_cnt[i] = 0;
    if (i < 448) g_stats[i] = 0.f;
}

__global__ void k_cnt(const int* __restrict__ knn) {
    int i = blockIdx.x * 256 + threadIdx.x;
    if (i < NK) atomicAdd(&g_cnt[knn[i]], 1);
}

// ---------------- stats helper ----------------
template<int CH>
__device__ __forceinline__ void stats_reduce(float* ls, float* lss, int off) {
    const unsigned FULL = 0xffffffffu;
    #pragma unroll
    for (int c = 0; c < CH; c++) {
        #pragma unroll
        for (int o = 16; o; o >>= 1) {
            ls[c]  += __shfl_down_sync(FULL, ls[c],  o);
            lss[c] += __shfl_down_sync(FULL, lss[c], o);
        }
    }
    __shared__ float sred[2 * 8 * CH];
    int wid = threadIdx.x >> 5, lane = threadIdx.x & 31;
    if (lane == 0) {
        #pragma unroll
        for (int c = 0; c < CH; c++) {
            sred[wid * CH + c]          = ls[c];
            sred[8 * CH + wid * CH + c] = lss[c];
        }
    }
    __syncthreads();
    if (threadIdx.x < CH) {
        float a = 0.f, b = 0.f;
        #pragma unroll
        for (int w = 0; w < 8; w++) {
            a += sred[w * CH + threadIdx.x];
            b += sred[8 * CH + w * CH + threadIdx.x];
        }
        atomicAdd(&g_stats[off + threadIdx.x], a);
        atomicAdd(&g_stats[off + CH + threadIdx.x], b);
    }
}

// ---------------- f-path conv (64 -> 64) per unique point ----------------
template<int STAGE>
__global__ __launch_bounds__(256) void k_fconv(const float* __restrict__ in,
                                               const float* __restrict__ W,
                                               const float* __restrict__ B) {
    __shared__ float wsm[64 * 64];
    __shared__ float xsm[4 * 64];
    __shared__ float red[256];
    int t = threadIdx.x, ch = t & 63, sub = t >> 6;
    for (int i = t; i < 4096; i += 256) {
        int h = i >> 6, c = i & 63;
        wsm[c * 64 + h] = W[i];
    }
    float sc = 0.f, sh = 0.f;
    if (STAGE == 1) { sc = g_ss[F1_OFF + ch]; sh = g_ss[F1_OFF + 64 + ch]; }
    float bias = B[ch];
    float ls = 0.f, lss = 0.f;
    const float* src = (STAGE == 0) ? in : g_g1;
    float* dst = (STAGE == 0) ? g_g1 : g_g2;
    int ngrp = (NP + 3) >> 2;
    for (int grp = blockIdx.x; grp < ngrp; grp += gridDim.x) {
        int p = grp * 4 + sub;
        __syncthreads();
        float xv = 0.f;
        if (p < NP) {
            xv = src[p * 64 + ch];
            if (STAGE == 1) xv = fmaxf(sc * xv + sh, 0.f);
        }
        xsm[t] = xv;
        __syncthreads();
        if (p < NP) {
            const float* x = &xsm[sub * 64];
            float acc = bias;
            #pragma unroll
            for (int c = 0; c < 64; c++) acc += wsm[c * 64 + ch] * x[c];
            dst[p * 64 + ch] = acc;
            float w = (float)g_cnt[p];
            ls += w * acc;
            lss += w * acc * acc;
        }
    }
    __syncthreads();
    red[t] = ls; __syncthreads();
    if (t < 64) {
        float v = red[t] + red[t + 64] + red[t + 128] + red[t + 192];
        atomicAdd(&g_stats[(STAGE == 0 ? F1_OFF : F2_OFF) + t], v);
    }
    __syncthreads();
    red[t] = lss; __syncthreads();
    if (t < 64) {
        float v = red[t] + red[t + 64] + red[t + 128] + red[t + 192];
        atomicAdd(&g_stats[(STAGE == 0 ? F1_OFF : F2_OFF) + 64 + t], v);
    }
}

// ---------------- w-path layer 1 ----------------
__global__ __launch_bounds__(256, 2) void k_w1(const float* __restrict__ xyz,
                                               const float* __restrict__ cov,
                                               const float* __restrict__ feats,
                                               const int* __restrict__ knn,
                                               const float* __restrict__ ww1,
                                               const float* __restrict__ wb1) {
    __shared__ float wsm[112];
    __shared__ float bsm[8];
    int t = threadIdx.x;
    if (t < 112) wsm[t] = ww1[t];
    if (t < 8)   bsm[t] = wb1[t];
    __syncthreads();
    float ls[8], lss[8];
    #pragma unroll
    for (int o = 0; o < 8; o++) { ls[o] = 0.f; lss[o] = 0.f; }
    for (int i = blockIdx.x * 256 + t; i < NK; i += gridDim.x * 256) {
        int n = i >> 4;
        int j  = knn[i];
        int j0 = knn[n << 4];
        float lx = xyz[j * 3 + 0] - xyz[j0 * 3 + 0];
        float ly = xyz[j * 3 + 1] - xyz[j0 * 3 + 1];
        float lz = xyz[j * 3 + 2] - xyz[j0 * 3 + 2];
        float nax = feats[j * 64 + 3],  nay = feats[j * 64 + 4],  naz = feats[j * 64 + 5];
        float nmx = feats[j0 * 64 + 3], nmy = feats[j0 * 64 + 4], nmz = feats[j0 * 64 + 5];
        float rn = sqrtf(lx * lx + ly * ly + lz * lz);
        float inv = 1.f / fmaxf(rn, 1e-12f);
        float rx = lx * inv, ry = ly * inv, rz = lz * inv;
        float dot = nmx * rx + nmy * ry + nmz * rz;
        float vx = nmx - dot * rx, vy = nmy - dot * ry, vz = nmz - dot * rz;
        float vi = 1.f / fmaxf(sqrtf(vx * vx + vy * vy + vz * vz), 1e-12f);
        vx *= vi; vy *= vi; vz *= vi;
        float wx = ry * vz - rz * vy;
        float wy = rz * vx - rx * vz;
        float wz = rx * vy - ry * vx;
        float wi = 1.f / fmaxf(sqrtf(wx * wx + wy * wy + wz * wz), 1e-12f);
        wx *= wi; wy *= wi; wz *= wi;
        float t1 = nax * nmx + nay * nmy + naz * nmz;
        float t3 = rx * nax + ry * nay + rz * naz;
        float t4 = lx * nmx + ly * nmy + lz * nmz;
        float t6 = nax * vx + nay * vy + naz * vz;
        float t7 = nax * wx + nay * wy + naz * wz;
        float cx = nay * nmz - naz * nmy;
        float cy = naz * nmx - nax * nmz;
        float cz = nax * nmy - nay * nmx;
        float t8 = lx * cx + ly * cy + lz * cz;
        const float* cg = &cov[j * 9];
        float s1 = lx * (cg[0] * lx + cg[1] * ly + cg[2] * lz)
                 + ly * (cg[3] * lx + cg[4] * ly + cg[5] * lz)
                 + lz * (cg[6] * lx + cg[7] * ly + cg[8] * lz);
        const float* c0 = &cov[j0 * 9];
        float s2 = lx * (c0[0] * lx + c0[1] * ly + c0[2] * lz)
                 + ly * (c0[3] * lx + c0[4] * ly + c0[5] * lz)
                 + lz * (c0[6] * lx + c0[7] * ly + c0[8] * lz);
        float win[14] = {lx, ly, lz, t1, dot, t3, t4, t3, t6, t7, t8, rn, s1, s2};
        float ya[8];
        #pragma unroll
        for (int o = 0; o < 8; o++) {
            float y = bsm[o];
            #pragma unroll
            for (int c = 0; c < 14; c++) y += wsm[o * 14 + c] * win[c];
            ya[o] = y;
            ls[o] += y; lss[o] += y * y;
        }
        float4* dst = (float4*)&g_y1w[i * 8];
        dst[0] = make_float4(ya[0], ya[1], ya[2], ya[3]);
        dst[1] = make_float4(ya[4], ya[5], ya[6], ya[7]);
    }
    stats_reduce<8>(ls, lss, W1_OFF);
}

// ---------------- w-path layer 2 ----------------
__global__ __launch_bounds__(256) void k_w2(const float* __restrict__ ww2,
                                            const float* __restrict__ wb2) {
    __shared__ float wsm[64], bsm[8], ssc[8], ssh[8];
    int t = threadIdx.x;
    if (t < 64) wsm[t] = ww2[t];
    if (t < 8) { bsm[t] = wb2[t]; ssc[t] = g_ss[W1_OFF + t]; ssh[t] = g_ss[W1_OFF + 8 + t]; }
    __syncthreads();
    float ls[8], lss[8];
    #pragma unroll
    for (int o = 0; o < 8; o++) { ls[o] = 0.f; lss[o] = 0.f; }
    for (int i = blockIdx.x * 256 + t; i < NK; i += gridDim.x * 256) {
        float a[8];
        float4 a0 = *(const float4*)&g_y1w[i * 8];
        float4 a1 = *(const float4*)&g_y1w[i * 8 + 4];
        a[0] = a0.x; a[1] = a0.y; a[2] = a0.z; a[3] = a0.w;
        a[4] = a1.x; a[5] = a1.y; a[6] = a1.z; a[7] = a1.w;
        #pragma unroll
        for (int c = 0; c < 8; c++) a[c] = fmaxf(ssc[c] * a[c] + ssh[c], 0.f);
        float ya[8];
        #pragma unroll
        for (int o = 0; o < 8; o++) {
            float y = bsm[o];
            #pragma unroll
            for (int c = 0; c < 8; c++) y += wsm[o * 8 + c] * a[c];
            ya[o] = y;
            ls[o] += y; lss[o] += y * y;
        }
        float4* dst = (float4*)&g_y2w[i * 8];
        dst[0] = make_float4(ya[0], ya[1], ya[2], ya[3]);
        dst[1] = make_float4(ya[4], ya[5], ya[6], ya[7]);
    }
    stats_reduce<8>(ls, lss, W2_OFF);
}

// ---------------- w-path layer 3: stats only ----------------
__global__ __launch_bounds__(256) void k_w3s(const float* __restrict__ ww3,
                                             const float* __restrict__ wb3) {
    __shared__ float wsm[128], bsm[16], ssc[8], ssh[8];
    int t = threadIdx.x;
    if (t < 128) wsm[t] = ww3[t];
    if (t < 16)  bsm[t] = wb3[t];
    if (t < 8) { ssc[t] = g_ss[W2_OFF + t]; ssh[t] = g_ss[W2_OFF + 8 + t]; }
    __syncthreads();
    float ls[16], lss[16];
    #pragma unroll
    for (int o = 0; o < 16; o++) { ls[o] = 0.f; lss[o] = 0.f; }
    for (int i = blockIdx.x * 256 + t; i < NK; i += gridDim.x * 256) {
        float a[8];
        float4 a0 = *(const float4*)&g_y2w[i * 8];
        float4 a1 = *(const float4*)&g_y2w[i * 8 + 4];
        a[0] = a0.x; a[1] = a0.y; a[2] = a0.z; a[3] = a0.w;
        a[4] = a1.x; a[5] = a1.y; a[6] = a1.z; a[7] = a1.w;
        #pragma unroll
        for (int c = 0; c < 8; c++) a[c] = fmaxf(ssc[c] * a[c] + ssh[c], 0.f);
        #pragma unroll
        for (int o = 0; o < 16; o++) {
            float y = bsm[o];
            #pragma unroll
            for (int c = 0; c < 8; c++) y += wsm[o * 8 + c] * a[c];
            ls[o] += y; lss[o] += y * y;
        }
    }
    stats_reduce<16>(ls, lss, W3_OFF);
}

// ---------------- finalize BN ----------------
__global__ void k_fin(int off, const float* __restrict__ gamma,
                      const float* __restrict__ beta, int nch, float invc) {
    int c = threadIdx.x;
    if (c < nch) {
        float m = g_stats[off + c] * invc;
        float v = g_stats[off + nch + c] * invc - m * m;
        float s = gamma[c] / sqrtf(v + EPS_BN);
        g_ss[off + c] = s;
        g_ss[off + nch + c] = beta[c] - m * s;
    }
}

// ---------------- fpost = relu(BN2(g_g2)) -> g_g1 ----------------
__global__ void k_post() {
    int i = blockIdx.x * 256 + threadIdx.x;
    if (i < NP * 64) {
        int c = i & 63;
        g_g1[i] = fmaxf(g_ss[F2_OFF + c] * g_g2[i] + g_ss[F2_OFF + 64 + c], 0.f);
    }
}

// ---------------- new = f @ w^T per point (64x16) ----------------
__global__ __launch_bounds__(128) void k_new(const int* __restrict__ knn,
                                             const float* __restrict__ ww3,
                                             const float* __restrict__ wb3) {
    __shared__ float sw[256];
    __shared__ int   sj[16];
    __shared__ float sww3[128], swb3[16], sc3[16], sh3[16], sc2[8], sh2[8];
    int t = threadIdx.x, n = blockIdx.x;
    if (t < 128) sww3[t] = ww3[t];
    if (t < 16) {
        swb3[t] = wb3[t];
        sc3[t] = g_ss[W3_OFF + t];
        sh3[t] = g_ss[W3_OFF + 16 + t];
        sj[t] = knn[n * 16 + t];
    }
    if (t >= 16 && t < 24) {
        int c = t - 16;
        sc2[c] = g_ss[W2_OFF + c];
        sh2[c] = g_ss[W2_OFF + 8 + c];
    }
    __syncthreads();
    if (t < 16) {
        int k = t;
        int base = (n * 16 + k) * 8;
        float a[8];
        float4 a0 = *(const float4*)&g_y2w[base];
        float4 a1 = *(const float4*)&g_y2w[base + 4];
        a[0] = a0.x; a[1] = a0.y; a[2] = a0.z; a[3] = a0.w;
        a[4] = a1.x; a[5] = a1.y; a[6] = a1.z; a[7] = a1.w;
        #pragma unroll
        for (int c = 0; c < 8; c++) a[c] = fmaxf(sc2[c] * a[c] + sh2[c], 0.f);
        #pragma unroll
        for (int m = 0; m < 16; m++) {
            float y = swb3[m];
            #pragma unroll
            for (int c = 0; c < 8; c++) y += sww3[m * 8 + c] * a[c];
            sw[m * 16 + k] = fmaxf(sc3[m] * y + sh3[m], 0.f);
        }
    }
    __syncthreads();
    int h = t >> 1, mb = (t & 1) * 8;
    float fv[16];
    #pragma unroll
    for (int k = 0; k < 16; k++)
        fv[k] = g_g1[sj[k] * 64 + h];   // fpost
    float out[8];
    #pragma unroll
    for (int mm = 0; mm < 8; mm++) {
        int m = mb + mm;
        float acc = 0.f;
        #pragma unroll
        for (int k = 0; k < 16; k++) acc += fv[k] * sw[m * 16 + k];
        out[mm] = acc;
    }
    float4* dst = (float4*)&g_new[n * 1024 + h * 16 + mb];
    dst[0] = make_float4(out[0], out[1], out[2], out[3]);
    dst[1] = make_float4(out[4], out[5], out[6], out[7]);
}

// ---------------- tf32 helpers ----------------
__device__ __forceinline__ unsigned f2tf(float x) {
    unsigned r;
    asm("cvt.rna.tf32.f32 %0, %1;" : "=r"(r) : "f"(x));
    return r;
}

__device__ __forceinline__ void mma_tf32(float* c, unsigned a0, unsigned a1,
                                         unsigned a2, unsigned a3,
                                         unsigned b0, unsigned b1) {
    asm volatile("mma.sync.aligned.m16n8k8.row.col.f32.tf32.tf32.f32 "
                 "{%0,%1,%2,%3}, {%4,%5,%6,%7}, {%8,%9}, {%0,%1,%2,%3};"
                 : "+f"(c[0]), "+f"(c[1]), "+f"(c[2]), "+f"(c[3])
                 : "r"(a0), "r"(a1), "r"(a2), "r"(a3), "r"(b0), "r"(b1));
}

// ---------------- final GEMM via tf32 mma: z = new @ lin_w^T ----------------
// block: 128 rows x 64 cols; K = 1024 in 16 chunks of 64; double buffered.
#define LPAD 68
#define ASZ (128 * LPAD)
#define BSZ (64 * LPAD)
#define SMEM_LIN ((2 * ASZ + 2 * BSZ) * 4)

__global__ __launch_bounds__(256, 2) void k_linmma(const float* __restrict__ lw,
                                                   const float* __restrict__ lb) {
    extern __shared__ unsigned sm[];
    unsigned* As[2] = { sm, sm + ASZ };
    unsigned* Bs[2] = { sm + 2 * ASZ, sm + 2 * ASZ + BSZ };

    int t = threadIdx.x;
    int rbase = blockIdx.x * 128;
    int warp = t >> 5, lane = t & 31;
    int grp = lane >> 2, qid = lane & 3;
    int m0 = warp * 16;

    float cf[8][4];
    #pragma unroll
    for (int nt = 0; nt < 8; nt++)
        #pragma unroll
        for (int j = 0; j < 4; j++) cf[nt][j] = 0.f;

    // A: row = t>>1 (128 rows), each thread 32 floats (8 f4)
    int arow = t >> 1, acol = (t & 1) * 32;
    bool arow_ok = (rbase + arow) < NP;
    // B: o = t&63, kpart = (t>>6)*16, each thread 16 floats (4 f4)
    int bo = t & 63, bk = (t >> 6) * 16;

    float4 pa[8], pb[4];

    auto load_g = [&](int kc) {
        const float* aptr = &g_new[(rbase + arow) * 1024 + kc + acol];
        #pragma unroll
        for (int q = 0; q < 8; q++)
            pa[q] = arow_ok ? *(const float4*)(aptr + 4 * q)
                            : make_float4(0.f, 0.f, 0.f, 0.f);
        const float* bptr = &lw[bo * 1024 + kc + bk];
        #pragma unroll
        for (int q = 0; q < 4; q++)
            pb[q] = *(const float4*)(bptr + 4 * q);
    };
    auto sts_buf = [&](int buf) {
        unsigned* ad = &As[buf][arow * LPAD + acol];
        #pragma unroll
        for (int q = 0; q < 8; q++) {
            ad[4 * q + 0] = f2tf(pa[q].x);
            ad[4 * q + 1] = f2tf(pa[q].y);
            ad[4 * q + 2] = f2tf(pa[q].z);
            ad[4 * q + 3] = f2tf(pa[q].w);
        }
        unsigned* bd = Bs[buf];
        #pragma unroll
        for (int q = 0; q < 4; q++) {
            bd[(bk + 4 * q + 0) * LPAD + bo] = f2tf(pb[q].x);
            bd[(bk + 4 * q + 1) * LPAD + bo] = f2tf(pb[q].y);
            bd[(bk + 4 * q + 2) * LPAD + bo] = f2tf(pb[q].z);
            bd[(bk + 4 * q + 3) * LPAD + bo] = f2tf(pb[q].w);
        }
    };

    load_g(0);
    sts_buf(0);
    __syncthreads();
    int cur = 0;
    for (int s = 0; s < 16; s++) {
        if (s < 15) load_g((s + 1) * 64);
        unsigned* A = As[cur];
        unsigned* B = Bs[cur];
        #pragma unroll
        for (int ks = 0; ks < 8; ks++) {
            int k0 = ks * 8;
            unsigned a0 = A[(m0 + grp) * LPAD + k0 + qid];
            unsigned a1 = A[(m0 + grp + 8) * LPAD + k0 + qid];
            unsigned a2 = A[(m0 + grp) * LPAD + k0 + qid + 4];
            unsigned a3 = A[(m0 + grp + 8) * LPAD + k0 + qid + 4];
            #pragma unroll
            for (int nt = 0; nt < 8; nt++) {
                unsigned b0 = B[(k0 + qid) * LPAD + nt * 8 + grp];
                unsigned b1 = B[(k0 + 4 + qid) * LPAD + nt * 8 + grp];
                mma_tf32(cf[nt], a0, a1, a2, a3, b0, b1);
            }
        }
        if (s < 15) {
            sts_buf(cur ^ 1);
            __syncthreads();
            cur ^= 1;
        }
    }

    // epilogue: z store + stats
    __syncthreads();
    float* sred = (float*)sm;  // 128 floats
    if (t < 128) sred[t] = 0.f;
    __syncthreads();
    int r0 = rbase + m0 + grp;
    int r1 = r0 + 8;
    #pragma unroll
    for (int nt = 0; nt < 8; nt++) {
        int c0 = nt * 8 + 2 * qid, c1 = c0 + 1;
        float b0v = lb[c0], b1v = lb[c1];
        if (r0 < NP) {
            float z0 = cf[nt][0] + b0v, z1 = cf[nt][1] + b1v;
            g_z[r0 * 64 + c0] = z0;
            g_z[r0 * 64 + c1] = z1;
            atomicAdd(&sred[c0], z0); atomicAdd(&sred[64 + c0], z0 * z0);
            atomicAdd(&sred[c1], z1); atomicAdd(&sred[64 + c1], z1 * z1);
        }
        if (r1 < NP) {
            float z2 = cf[nt][2] + b0v, z3 = cf[nt][3] + b1v;
            g_z[r1 * 64 + c0] = z2;
            g_z[r1 * 64 + c1] = z3;
            atomicAdd(&sred[c0], z2); atomicAdd(&sred[64 + c0], z2 * z2);
            atomicAdd(&sred[c1], z3); atomicAdd(&sred[64 + c1], z3 * z3);
        }
    }
    __syncthreads();
    if (t < 128) atomicAdd(&g_stats[Z_OFF + t], sred[t]);
}

// ---------------- final BN + relu -> output ----------------
__global__ void k_out(float* __restrict__ out) {
    int i = blockIdx.x * 256 + threadIdx.x;
    if (i < NP * 64) {
        int c = i & 63;
        out[i] = fmaxf(g_ss[Z_OFF + c] * g_z[i] + g_ss[Z_OFF + 64 + c], 0.f);
    }
}

// ---------------- launch ----------------
extern "C" void kernel_launch(void* const* d_in, const int* in_sizes, int n_in,
                              void* d_out, int out_size) {
    const float* xyz   = (const float*)d_in[0];
    const float* cov   = (const float*)d_in[1];
    const float* feats = (const float*)d_in[2];
    const int*   knn   = (const int*)  d_in[3];
    const float* fw1 = (const float*)d_in[4];
    const float* fb1 = (const float*)d_in[5];
    const float* fg1 = (const float*)d_in[6];
    const float* fbe1 = (const float*)d_in[7];
    const float* fw2 = (const float*)d_in[8];
    const float* fb2 = (const float*)d_in[9];
    const float* fg2 = (const float*)d_in[10];
    const float* fbe2 = (const float*)d_in[11];
    const float* ww1 = (const float*)d_in[12];
    const float* wb1 = (const float*)d_in[13];
    const float* wg1 = (const float*)d_in[14];
    const float* wbe1 = (const float*)d_in[15];
    const float* ww2 = (const float*)d_in[16];
    const float* wb2 = (const float*)d_in[17];
    const float* wg2 = (const float*)d_in[18];
    const float* wbe2 = (const float*)d_in[19];
    const float* ww3 = (const float*)d_in[20];
    const float* wb3 = (const float*)d_in[21];
    const float* wg3 = (const float*)d_in[22];
    const float* wbe3 = (const float*)d_in[23];
    const float* lin_w = (const float*)d_in[24];
    const float* lin_b = (const float*)d_in[25];
    const float* bng = (const float*)d_in[26];
    const float* bnb = (const float*)d_in[27];
    float* out = (float*)d_out;

    const float invNK = 1.f / (float)NK;
    const float invN  = 1.f / (float)NP;

    cudaFuncSetAttribute(k_linmma, cudaFuncAttributeMaxDynamicSharedMemorySize, SMEM_LIN);

    k_zero<<<(NP + 255) / 256, 256>>>();
    k_cnt<<<(NK + 255) / 256, 256>>>(knn);

    // stage 1
    k_fconv<0><<<1024, 256>>>(feats, fw1, fb1);
    k_w1<<<2048, 256>>>(xyz, cov, feats, knn, ww1, wb1);
    k_fin<<<1, 64>>>(F1_OFF, fg1, fbe1, 64, invNK);
    k_fin<<<1, 64>>>(W1_OFF, wg1, wbe1, 8, invNK);

    // stage 2
    k_fconv<1><<<1024, 256>>>(nullptr, fw2, fb2);
    k_w2<<<2048, 256>>>(ww2, wb2);
    k_fin<<<1, 64>>>(F2_OFF, fg2, fbe2, 64, invNK);
    k_fin<<<1, 64>>>(W2_OFF, wg2, wbe2, 8, invNK);

    // fpost + stage 3 (w path)
    k_post<<<(NP * 64 + 255) / 256, 256>>>();
    k_w3s<<<2048, 256>>>(ww3, wb3);
    k_fin<<<1, 64>>>(W3_OFF, wg3, wbe3, 16, invNK);

    // einsum + linear(mma) + final BN
    k_new<<<NP, 128>>>(knn, ww3, wb3);
    k_linmma<<<(NP + 127) / 128, 256, SMEM_LIN>>>(lin_w, lin_b);
    k_fin<<<1, 64>>>(Z_OFF, bng, bnb, 64, invN);
    k_out<<<(NP * 64 + 255) / 256, 256>>>(out);
}

// round 3
// speedup vs baseline: 1.3484x; 1.3484x over previous
#include <cuda_runtime.h>

#define NP 100000
#define KN 16
#define NK (NP*KN)

// ---------------- device scratch ----------------
__device__ int      g_cnt[NP];
__device__ float    g_g1[NP*64];          // f-path layer1 pre-BN, later reused as fpost
__device__ float    g_g2[NP*64];          // f-path layer2 pre-BN
__device__ float    g_y1w[NK*8];
__device__ float    g_y2w[NK*8];
__device__ unsigned g_newt[NP*1024];      // new_flat as tf32 bits, K-permuted
__device__ unsigned g_lwt[64*1024];       // lin_w as tf32 bits, K-permuted
__device__ float    g_z[NP*64];
__device__ float    g_stats[448];
__device__ float    g_ss[448];

#define F1_OFF 0
#define W1_OFF 128
#define F2_OFF 144
#define W2_OFF 272
#define W3_OFF 288
#define Z_OFF  320

#define EPS_BN 1e-5f

// ---------------- init ----------------
__global__ void k_zero() {
    int i = blockIdx.x * 256 + threadIdx.x;
    if (i < NP)  g_cnt[i] = 0;
    if (i < 448) g_stats[i] = 0.f;
}

__global__ void k_cnt(const int* __restrict__ knn) {
    int i = blockIdx.x * 256 + threadIdx.x;
    if (i < NK) atomicAdd(&g_cnt[knn[i]], 1);
}

// ---------------- stats helper ----------------
template<int CH>
__device__ __forceinline__ void stats_reduce(float* ls, float* lss, int off) {
    const unsigned FULL = 0xffffffffu;
    #pragma unroll
    for (int c = 0; c < CH; c++) {
        #pragma unroll
        for (int o = 16; o; o >>= 1) {
            ls[c]  += __shfl_down_sync(FULL, ls[c],  o);
            lss[c] += __shfl_down_sync(FULL, lss[c], o);
        }
    }
    __shared__ float sred[2 * 8 * CH];
    int wid = threadIdx.x >> 5, lane = threadIdx.x & 31;
    if (lane == 0) {
        #pragma unroll
        for (int c = 0; c < CH; c++) {
            sred[wid * CH + c]          = ls[c];
            sred[8 * CH + wid * CH + c] = lss[c];
        }
    }
    __syncthreads();
    if (threadIdx.x < CH) {
        float a = 0.f, b = 0.f;
        #pragma unroll
        for (int w = 0; w < 8; w++) {
            a += sred[w * CH + threadIdx.x];
            b += sred[8 * CH + w * CH + threadIdx.x];
        }
        atomicAdd(&g_stats[off + threadIdx.x], a);
        atomicAdd(&g_stats[off + CH + threadIdx.x], b);
    }
}

// ---------------- f-path conv (64 -> 64) per unique point ----------------
template<int STAGE>
__global__ __launch_bounds__(256) void k_fconv(const float* __restrict__ in,
                                               const float* __restrict__ W,
                                               const float* __restrict__ B) {
    __shared__ float wsm[64 * 64];
    __shared__ float xsm[4 * 64];
    __shared__ float red[256];
    int t = threadIdx.x, ch = t & 63, sub = t >> 6;
    for (int i = t; i < 4096; i += 256) {
        int h = i >> 6, c = i & 63;
        wsm[c * 64 + h] = W[i];
    }
    float sc = 0.f, sh = 0.f;
    if (STAGE == 1) { sc = g_ss[F1_OFF + ch]; sh = g_ss[F1_OFF + 64 + ch]; }
    float bias = B[ch];
    float ls = 0.f, lss = 0.f;
    const float* src = (STAGE == 0) ? in : g_g1;
    float* dst = (STAGE == 0) ? g_g1 : g_g2;
    int ngrp = (NP + 3) >> 2;
    for (int grp = blockIdx.x; grp < ngrp; grp += gridDim.x) {
        int p = grp * 4 + sub;
        __syncthreads();
        float xv = 0.f;
        if (p < NP) {
            xv = src[p * 64 + ch];
            if (STAGE == 1) xv = fmaxf(sc * xv + sh, 0.f);
        }
        xsm[t] = xv;
        __syncthreads();
        if (p < NP) {
            const float* x = &xsm[sub * 64];
            float acc = bias;
            #pragma unroll
            for (int c = 0; c < 64; c++) acc += wsm[c * 64 + ch] * x[c];
            dst[p * 64 + ch] = acc;
            float w = (float)g_cnt[p];
            ls += w * acc;
            lss += w * acc * acc;
        }
    }
    __syncthreads();
    red[t] = ls; __syncthreads();
    if (t < 64) {
        float v = red[t] + red[t + 64] + red[t + 128] + red[t + 192];
        atomicAdd(&g_stats[(STAGE == 0 ? F1_OFF : F2_OFF) + t], v);
    }
    __syncthreads();
    red[t] = lss; __syncthreads();
    if (t < 64) {
        float v = red[t] + red[t + 64] + red[t + 128] + red[t + 192];
        atomicAdd(&g_stats[(STAGE == 0 ? F1_OFF : F2_OFF) + 64 + t], v);
    }
}

// ---------------- w-path layer 1 ----------------
__global__ __launch_bounds__(256, 3) void k_w1(const float* __restrict__ xyz,
                                               const float* __restrict__ cov,
                                               const float* __restrict__ feats,
                                               const int* __restrict__ knn,
                                               const float* __restrict__ ww1,
                                               const float* __restrict__ wb1) {
    __shared__ float wsm[112];
    __shared__ float bsm[8];
    int t = threadIdx.x;
    if (t < 112) wsm[t] = ww1[t];
    if (t < 8)   bsm[t] = wb1[t];
    __syncthreads();
    float ls[8], lss[8];
    #pragma unroll
    for (int o = 0; o < 8; o++) { ls[o] = 0.f; lss[o] = 0.f; }
    for (int i = blockIdx.x * 256 + t; i < NK; i += gridDim.x * 256) {
        int n = i >> 4;
        int j  = knn[i];
        int j0 = knn[n << 4];
        float lx = xyz[j * 3 + 0] - xyz[j0 * 3 + 0];
        float ly = xyz[j * 3 + 1] - xyz[j0 * 3 + 1];
        float lz = xyz[j * 3 + 2] - xyz[j0 * 3 + 2];
        float nax = feats[j * 64 + 3],  nay = feats[j * 64 + 4],  naz = feats[j * 64 + 5];
        float nmx = feats[j0 * 64 + 3], nmy = feats[j0 * 64 + 4], nmz = feats[j0 * 64 + 5];
        float rn = sqrtf(lx * lx + ly * ly + lz * lz);
        float inv = 1.f / fmaxf(rn, 1e-12f);
        float rx = lx * inv, ry = ly * inv, rz = lz * inv;
        float dot = nmx * rx + nmy * ry + nmz * rz;
        float vx = nmx - dot * rx, vy = nmy - dot * ry, vz = nmz - dot * rz;
        float vi = 1.f / fmaxf(sqrtf(vx * vx + vy * vy + vz * vz), 1e-12f);
        vx *= vi; vy *= vi; vz *= vi;
        float wx = ry * vz - rz * vy;
        float wy = rz * vx - rx * vz;
        float wz = rx * vy - ry * vx;
        float wi = 1.f / fmaxf(sqrtf(wx * wx + wy * wy + wz * wz), 1e-12f);
        wx *= wi; wy *= wi; wz *= wi;
        float t1 = nax * nmx + nay * nmy + naz * nmz;
        float t3 = rx * nax + ry * nay + rz * naz;
        float t4 = lx * nmx + ly * nmy + lz * nmz;
        float t6 = nax * vx + nay * vy + naz * vz;
        float t7 = nax * wx + nay * wy + naz * wz;
        float cx = nay * nmz - naz * nmy;
        float cy = naz * nmx - nax * nmz;
        float cz = nax * nmy - nay * nmx;
        float t8 = lx * cx + ly * cy + lz * cz;
        const float* cg = &cov[j * 9];
        float s1 = lx * (cg[0] * lx + cg[1] * ly + cg[2] * lz)
                 + ly * (cg[3] * lx + cg[4] * ly + cg[5] * lz)
                 + lz * (cg[6] * lx + cg[7] * ly + cg[8] * lz);
        const float* c0 = &cov[j0 * 9];
        float s2 = lx * (c0[0] * lx + c0[1] * ly + c0[2] * lz)
                 + ly * (c0[3] * lx + c0[4] * ly + c0[5] * lz)
                 + lz * (c0[6] * lx + c0[7] * ly + c0[8] * lz);
        float win[14] = {lx, ly, lz, t1, dot, t3, t4, t3, t6, t7, t8, rn, s1, s2};
        float ya[8];
        #pragma unroll
        for (int o = 0; o < 8; o++) {
            float y = bsm[o];
            #pragma unroll
            for (int c = 0; c < 14; c++) y += wsm[o * 14 + c] * win[c];
            ya[o] = y;
            ls[o] += y; lss[o] += y * y;
        }
        float4* dst = (float4*)&g_y1w[i * 8];
        dst[0] = make_float4(ya[0], ya[1], ya[2], ya[3]);
        dst[1] = make_float4(ya[4], ya[5], ya[6], ya[7]);
    }
    stats_reduce<8>(ls, lss, W1_OFF);
}

// ---------------- w-path layer 2 ----------------
__global__ __launch_bounds__(256) void k_w2(const float* __restrict__ ww2,
                                            const float* __restrict__ wb2) {
    __shared__ float wsm[64], bsm[8], ssc[8], ssh[8];
    int t = threadIdx.x;
    if (t < 64) wsm[t] = ww2[t];
    if (t < 8) { bsm[t] = wb2[t]; ssc[t] = g_ss[W1_OFF + t]; ssh[t] = g_ss[W1_OFF + 8 + t]; }
    __syncthreads();
    float ls[8], lss[8];
    #pragma unroll
    for (int o = 0; o < 8; o++) { ls[o] = 0.f; lss[o] = 0.f; }
    for (int i = blockIdx.x * 256 + t; i < NK; i += gridDim.x * 256) {
        float a[8];
        float4 a0 = *(const float4*)&g_y1w[i * 8];
        float4 a1 = *(const float4*)&g_y1w[i * 8 + 4];
        a[0] = a0.x; a[1] = a0.y; a[2] = a0.z; a[3] = a0.w;
        a[4] = a1.x; a[5] = a1.y; a[6] = a1.z; a[7] = a1.w;
        #pragma unroll
        for (int c = 0; c < 8; c++) a[c] = fmaxf(ssc[c] * a[c] + ssh[c], 0.f);
        float ya[8];
        #pragma unroll
        for (int o = 0; o < 8; o++) {
            float y = bsm[o];
            #pragma unroll
            for (int c = 0; c < 8; c++) y += wsm[o * 8 + c] * a[c];
            ya[o] = y;
            ls[o] += y; lss[o] += y * y;
        }
        float4* dst = (float4*)&g_y2w[i * 8];
        dst[0] = make_float4(ya[0], ya[1], ya[2], ya[3]);
        dst[1] = make_float4(ya[4], ya[5], ya[6], ya[7]);
    }
    stats_reduce<8>(ls, lss, W2_OFF);
}

// ---------------- w-path layer 3: stats only ----------------
__global__ __launch_bounds__(256) void k_w3s(const float* __restrict__ ww3,
                                             const float* __restrict__ wb3) {
    __shared__ float wsm[128], bsm[16], ssc[8], ssh[8];
    int t = threadIdx.x;
    if (t < 128) wsm[t] = ww3[t];
    if (t < 16)  bsm[t] = wb3[t];
    if (t < 8) { ssc[t] = g_ss[W2_OFF + t]; ssh[t] = g_ss[W2_OFF + 8 + t]; }
    __syncthreads();
    float ls[16], lss[16];
    #pragma unroll
    for (int o = 0; o < 16; o++) { ls[o] = 0.f; lss[o] = 0.f; }
    for (int i = blockIdx.x * 256 + t; i < NK; i += gridDim.x * 256) {
        float a[8];
        float4 a0 = *(const float4*)&g_y2w[i * 8];
        float4 a1 = *(const float4*)&g_y2w[i * 8 + 4];
        a[0] = a0.x; a[1] = a0.y; a[2] = a0.z; a[3] = a0.w;
        a[4] = a1.x; a[5] = a1.y; a[6] = a1.z; a[7] = a1.w;
        #pragma unroll
        for (int c = 0; c < 8; c++) a[c] = fmaxf(ssc[c] * a[c] + ssh[c], 0.f);
        #pragma unroll
        for (int o = 0; o < 16; o++) {
            float y = bsm[o];
            #pragma unroll
            for (int c = 0; c < 8; c++) y += wsm[o * 8 + c] * a[c];
            ls[o] += y; lss[o] += y * y;
        }
    }
    stats_reduce<16>(ls, lss, W3_OFF);
}

// ---------------- finalize BN ----------------
__global__ void k_fin(int off, const float* __restrict__ gamma,
                      const float* __restrict__ beta, int nch, float invc) {
    int c = threadIdx.x;
    if (c < nch) {
        float m = g_stats[off + c] * invc;
        float v = g_stats[off + nch + c] * invc - m * m;
        float s = gamma[c] / sqrtf(v + EPS_BN);
        g_ss[off + c] = s;
        g_ss[off + nch + c] = beta[c] - m * s;
    }
}

// ---------------- fpost = relu(BN2(g_g2)) -> g_g1 ----------------
__global__ void k_post() {
    int i = blockIdx.x * 256 + threadIdx.x;
    if (i < NP * 64) {
        int c = i & 63;
        g_g1[i] = fmaxf(g_ss[F2_OFF + c] * g_g2[i] + g_ss[F2_OFF + 64 + c], 0.f);
    }
}

// ---------------- tf32 helpers ----------------
__device__ __forceinline__ unsigned f2tf(float x) {
    unsigned r;
    asm("cvt.rna.tf32.f32 %0, %1;" : "=r"(r) : "f"(x));
    return r;
}

__device__ __forceinline__ void mma_tf32(float* c, unsigned a0, unsigned a1,
                                         unsigned a2, unsigned a3,
                                         unsigned b0, unsigned b1) {
    asm volatile("mma.sync.aligned.m16n8k8.row.col.f32.tf32.tf32.f32 "
                 "{%0,%1,%2,%3}, {%4,%5,%6,%7}, {%8,%9}, {%0,%1,%2,%3};"
                 : "+f"(c[0]), "+f"(c[1]), "+f"(c[2]), "+f"(c[3])
                 : "r"(a0), "r"(a1), "r"(a2), "r"(a3), "r"(b0), "r"(b1));
}

__device__ __forceinline__ void cp16(void* sptr, const void* gptr) {
    unsigned saddr = (unsigned)__cvta_generic_to_shared(sptr);
    asm volatile("cp.async.cg.shared.global [%0], [%1], 16;" :: "r"(saddr), "l"(gptr));
}

// ---------------- new = f @ w^T per point; store tf32 bits, K-permuted ----------------
// Storage position p within each 8-col group holds logical col sigma(p) = {0,4,1,5,2,6,3,7}.
__global__ __launch_bounds__(128) void k_new(const int* __restrict__ knn,
                                             const float* __restrict__ ww3,
                                             const float* __restrict__ wb3) {
    __shared__ float sw[256];
    __shared__ int   sj[16];
    __shared__ float sww3[128], swb3[16], sc3[16], sh3[16], sc2[8], sh2[8];
    int t = threadIdx.x, n = blockIdx.x;
    if (t < 128) sww3[t] = ww3[t];
    if (t < 16) {
        swb3[t] = wb3[t];
        sc3[t] = g_ss[W3_OFF + t];
        sh3[t] = g_ss[W3_OFF + 16 + t];
        sj[t] = knn[n * 16 + t];
    }
    if (t >= 16 && t < 24) {
        int c = t - 16;
        sc2[c] = g_ss[W2_OFF + c];
        sh2[c] = g_ss[W2_OFF + 8 + c];
    }
    __syncthreads();
    if (t < 16) {
        int k = t;
        int base = (n * 16 + k) * 8;
        float a[8];
        float4 a0 = *(const float4*)&g_y2w[base];
        float4 a1 = *(const float4*)&g_y2w[base + 4];
        a[0] = a0.x; a[1] = a0.y; a[2] = a0.z; a[3] = a0.w;
        a[4] = a1.x; a[5] = a1.y; a[6] = a1.z; a[7] = a1.w;
        #pragma unroll
        for (int c = 0; c < 8; c++) a[c] = fmaxf(sc2[c] * a[c] + sh2[c], 0.f);
        #pragma unroll
        for (int m = 0; m < 16; m++) {
            float y = swb3[m];
            #pragma unroll
            for (int c = 0; c < 8; c++) y += sww3[m * 8 + c] * a[c];
            sw[m * 16 + k] = fmaxf(sc3[m] * y + sh3[m], 0.f);
        }
    }
    __syncthreads();
    int h = t >> 1, mb = (t & 1) * 8;
    float fv[16];
    #pragma unroll
    for (int k = 0; k < 16; k++)
        fv[k] = g_g1[sj[k] * 64 + h];   // fpost
    float out[8];
    #pragma unroll
    for (int mm = 0; mm < 8; mm++) {
        int m = mb + mm;
        float acc = 0.f;
        #pragma unroll
        for (int k = 0; k < 16; k++) acc += fv[k] * sw[m * 16 + k];
        out[mm] = acc;
    }
    // permuted tf32 store: positions hold logical {0,4,1,5,2,6,3,7}
    uint4 u0, u1;
    u0.x = f2tf(out[0]); u0.y = f2tf(out[4]); u0.z = f2tf(out[1]); u0.w = f2tf(out[5]);
    u1.x = f2tf(out[2]); u1.y = f2tf(out[6]); u1.z = f2tf(out[3]); u1.w = f2tf(out[7]);
    uint4* dst = (uint4*)&g_newt[n * 1024 + h * 16 + mb];
    dst[0] = u0;
    dst[1] = u1;
}

// ---------------- prep: lin_w -> tf32 bits, K-permuted, same row-major [o][k] ----------------
__global__ void k_prep(const float* __restrict__ lw) {
    int i = blockIdx.x * 256 + threadIdx.x;   // i over 64*1024
    if (i < 64 * 1024) {
        int c = i & 1023;
        int l = c & 7;
        int p = ((l & 3) << 1) | (l >> 2);
        int kpos = (c & ~7) | p;
        g_lwt[(i & ~1023) | kpos] = f2tf(lw[i]);
    }
}

// ---------------- GEMM: z = new(NPx1024) @ lin_w^T(1024x64), tf32 mma + cp.async ----------------
#define GP 36                      // pad words per row
#define GA (128*GP)
#define GB (64*GP)
#define SMEM_G ((2*GA + 2*GB)*4)   // 55296 bytes

__global__ __launch_bounds__(256, 3) void k_gemm(const float* __restrict__ lb) {
    extern __shared__ unsigned sm[];
    unsigned* As[2] = { sm, sm + GA };
    unsigned* Bs[2] = { sm + 2 * GA, sm + 2 * GA + GB };
    int t = threadIdx.x;
    int rbase = blockIdx.x * 128;
    int lane = t & 31, grp = lane >> 2, qid = lane & 3;
    int m0 = (t >> 5) * 16;

    if (rbase + 128 > NP) {
        for (int i = t; i < 2 * GA; i += 256) sm[i] = 0u;
        __syncthreads();
    }

    float cf[8][4];
    #pragma unroll
    for (int nt = 0; nt < 8; nt++)
        #pragma unroll
        for (int j = 0; j < 4; j++) cf[nt][j] = 0.f;

    auto load = [&](int buf, int s) {
        int kc = s * 32;
        #pragma unroll
        for (int r4 = 0; r4 < 4; r4++) {
            int seg = t + r4 * 256;
            int row = seg >> 3, c16 = seg & 7;
            if (rbase + row < NP)
                cp16(As[buf] + row * GP + c16 * 4,
                     g_newt + (size_t)(rbase + row) * 1024 + kc + c16 * 4);
        }
        #pragma unroll
        for (int r2 = 0; r2 < 2; r2++) {
            int seg = t + r2 * 256;
            int row = seg >> 3, c16 = seg & 7;
            cp16(Bs[buf] + row * GP + c16 * 4,
                 g_lwt + row * 1024 + kc + c16 * 4);
        }
        asm volatile("cp.async.commit_group;");
    };

    load(0, 0);
    int cur = 0;
    for (int s = 0; s < 32; s++) {
        if (s < 31) {
            load(cur ^ 1, s + 1);
            asm volatile("cp.async.wait_group 1;");
        } else {
            asm volatile("cp.async.wait_group 0;");
        }
        __syncthreads();
        unsigned* A = As[cur];
        unsigned* B = Bs[cur];
        #pragma unroll
        for (int ks = 0; ks < 4; ks++) {
            uint2 aLo = *(uint2*)&A[(m0 + grp) * GP + ks * 8 + qid * 2];      // (k=qid, k=qid+4) row m0+grp
            uint2 aHi = *(uint2*)&A[(m0 + grp + 8) * GP + ks * 8 + qid * 2];  // row m0+grp+8
            #pragma unroll
            for (int nt = 0; nt < 8; nt++) {
                uint2 b = *(uint2*)&B[(nt * 8 + grp) * GP + ks * 8 + qid * 2];
                mma_tf32(cf[nt], aLo.x, aHi.x, aLo.y, aHi.y, b.x, b.y);
            }
        }
        __syncthreads();
        cur ^= 1;
    }

    int r0 = rbase + m0 + grp, r1 = r0 + 8;
    #pragma unroll
    for (int nt = 0; nt < 8; nt++) {
        int c0 = nt * 8 + 2 * qid;
        float b0v = __ldg(&lb[c0]), b1v = __ldg(&lb[c0 + 1]);
        if (r0 < NP) *(float2*)&g_z[r0 * 64 + c0] = make_float2(cf[nt][0] + b0v, cf[nt][1] + b1v);
        if (r1 < NP) *(float2*)&g_z[r1 * 64 + c0] = make_float2(cf[nt][2] + b0v, cf[nt][3] + b1v);
    }
}

// ---------------- stats over z ----------------
__global__ __launch_bounds__(256) void k_zstats() {
    __shared__ float sred[128];
    int t = threadIdx.x;
    if (t < 128) sred[t] = 0.f;
    __syncthreads();
    int cg = (t & 15) * 4;
    float s[4] = {0.f, 0.f, 0.f, 0.f}, ss[4] = {0.f, 0.f, 0.f, 0.f};
    for (int i = blockIdx.x * 256 + t; i < NP * 16; i += gridDim.x * 256) {
        float4 v = *(const float4*)&g_z[i * 4];
        s[0] += v.x; ss[0] += v.x * v.x;
        s[1] += v.y; ss[1] += v.y * v.y;
        s[2] += v.z; ss[2] += v.z * v.z;
        s[3] += v.w; ss[3] += v.w * v.w;
    }
    // fold lane 16-groups: shfl_down 16 keeps (lane&15) column mapping
    const unsigned FULL = 0xffffffffu;
    #pragma unroll
    for (int j = 0; j < 4; j++) {
        s[j]  += __shfl_down_sync(FULL, s[j], 16);
        ss[j] += __shfl_down_sync(FULL, ss[j], 16);
    }
    if ((t & 31) < 16) {
        #pragma unroll
        for (int j = 0; j < 4; j++) {
            atomicAdd(&sred[cg + j], s[j]);
            atomicAdd(&sred[64 + cg + j], ss[j]);
        }
    }
    __syncthreads();
    if (t < 128) atomicAdd(&g_stats[Z_OFF + t], sred[t]);
}

// ---------------- final BN + relu -> output ----------------
__global__ void k_out(float* __restrict__ out) {
    int i = blockIdx.x * 256 + threadIdx.x;
    if (i < NP * 64) {
        int c = i & 63;
        out[i] = fmaxf(g_ss[Z_OFF + c] * g_z[i] + g_ss[Z_OFF + 64 + c], 0.f);
    }
}

// ---------------- launch ----------------
extern "C" void kernel_launch(void* const* d_in, const int* in_sizes, int n_in,
                              void* d_out, int out_size) {
    const float* xyz   = (const float*)d_in[0];
    const float* cov   = (const float*)d_in[1];
    const float* feats = (const float*)d_in[2];
    const int*   knn   = (const int*)  d_in[3];
    const float* fw1 = (const float*)d_in[4];
    const float* fb1 = (const float*)d_in[5];
    const float* fg1 = (const float*)d_in[6];
    const float* fbe1 = (const float*)d_in[7];
    const float* fw2 = (const float*)d_in[8];
    const float* fb2 = (const float*)d_in[9];
    const float* fg2 = (const float*)d_in[10];
    const float* fbe2 = (const float*)d_in[11];
    const float* ww1 = (const float*)d_in[12];
    const float* wb1 = (const float*)d_in[13];
    const float* wg1 = (const float*)d_in[14];
    const float* wbe1 = (const float*)d_in[15];
    const float* ww2 = (const float*)d_in[16];
    const float* wb2 = (const float*)d_in[17];
    const float* wg2 = (const float*)d_in[18];
    const float* wbe2 = (const float*)d_in[19];
    const float* ww3 = (const float*)d_in[20];
    const float* wb3 = (const float*)d_in[21];
    const float* wg3 = (const float*)d_in[22];
    const float* wbe3 = (const float*)d_in[23];
    const float* lin_w = (const float*)d_in[24];
    const float* lin_b = (const float*)d_in[25];
    const float* bng = (const float*)d_in[26];
    const float* bnb = (const float*)d_in[27];
    float* out = (float*)d_out;

    const float invNK = 1.f / (float)NK;
    const float invN  = 1.f / (float)NP;

    cudaFuncSetAttribute(k_gemm, cudaFuncAttributeMaxDynamicSharedMemorySize, SMEM_G);

    k_zero<<<(NP + 255) / 256, 256>>>();
    k_cnt<<<(NK + 255) / 256, 256>>>(knn);
    k_prep<<<256, 256>>>(lin_w);

    // stage 1
    k_fconv<0><<<1024, 256>>>(feats, fw1, fb1);
    k_w1<<<2048, 256>>>(xyz, cov, feats, knn, ww1, wb1);
    k_fin<<<1, 64>>>(F1_OFF, fg1, fbe1, 64, invNK);
    k_fin<<<1, 64>>>(W1_OFF, wg1, wbe1, 8, invNK);

    // stage 2
    k_fconv<1><<<1024, 256>>>(nullptr, fw2, fb2);
    k_w2<<<2048, 256>>>(ww2, wb2);
    k_fin<<<1, 64>>>(F2_OFF, fg2, fbe2, 64, invNK);
    k_fin<<<1, 64>>>(W2_OFF, wg2, wbe2, 8, invNK);

    // fpost + stage 3 (w path)
    k_post<<<(NP * 64 + 255) / 256, 256>>>();
    k_w3s<<<2048, 256>>>(ww3, wb3);
    k_fin<<<1, 64>>>(W3_OFF, wg3, wbe3, 16, invNK);

    // einsum + GEMM + final BN
    k_new<<<NP, 128>>>(knn, ww3, wb3);
    k_gemm<<<(NP + 127) / 128, 256, SMEM_G>>>(lin_b);
    k_zstats<<<512, 256>>>();
    k_fin<<<1, 64>>>(Z_OFF, bng, bnb, 64, invN);
    k_out<<<(NP * 64 + 255) / 256, 256>>>(out);
}

// round 4
// speedup vs baseline: 1.6315x; 1.2099x over previous
#include <cuda_runtime.h>
#include <cuda_fp16.h>

#define NP 100000
#define KN 16
#define NK (NP*KN)
#define NG 3125          // NP/32 point-groups for fconv (exact)

// ---------------- device scratch ----------------
__device__ int      g_cnt[NP];
__device__ float    g_g1[NP*64];          // f-path layer1 pre-BN, later reused as fpost
__device__ float    g_g2[NP*64];          // f-path layer2 pre-BN
__device__ float    g_y1w[NK*8];
__device__ float    g_y2w[NK*8];
__device__ unsigned g_newh[NP*512];       // new_flat as half2 words, K-permuted
__device__ unsigned g_lwth[64*512];       // lin_w as half2 words, K-permuted
__device__ float    g_z[NP*64];
__device__ float    g_stats[448];
__device__ float    g_ss[448];

#define F1_OFF 0
#define W1_OFF 128
#define F2_OFF 144
#define W2_OFF 272
#define W3_OFF 288
#define Z_OFF  320

#define EPS_BN 1e-5f

// ---------------- init ----------------
__global__ void k_zero() {
    int i = blockIdx.x * 256 + threadIdx.x;
    if (i < NP)  g_cnt[i] = 0;
    if (i < 448) g_stats[i] = 0.f;
}

__global__ void k_cnt(const int* __restrict__ knn) {
    int i = blockIdx.x * 256 + threadIdx.x;
    if (i < NK) atomicAdd(&g_cnt[knn[i]], 1);
}

// ---------------- stats helper ----------------
template<int CH>
__device__ __forceinline__ void stats_reduce(float* ls, float* lss, int off) {
    const unsigned FULL = 0xffffffffu;
    #pragma unroll
    for (int c = 0; c < CH; c++) {
        #pragma unroll
        for (int o = 16; o; o >>= 1) {
            ls[c]  += __shfl_down_sync(FULL, ls[c],  o);
            lss[c] += __shfl_down_sync(FULL, lss[c], o);
        }
    }
    __shared__ float sred[2 * 8 * CH];
    int wid = threadIdx.x >> 5, lane = threadIdx.x & 31;
    if (lane == 0) {
        #pragma unroll
        for (int c = 0; c < CH; c++) {
            sred[wid * CH + c]          = ls[c];
            sred[8 * CH + wid * CH + c] = lss[c];
        }
    }
    __syncthreads();
    if (threadIdx.x < CH) {
        float a = 0.f, b = 0.f;
        #pragma unroll
        for (int w = 0; w < 8; w++) {
            a += sred[w * CH + threadIdx.x];
            b += sred[8 * CH + w * CH + threadIdx.x];
        }
        atomicAdd(&g_stats[off + threadIdx.x], a);
        atomicAdd(&g_stats[off + CH + threadIdx.x], b);
    }
}

// ---------------- f-path conv (64 -> 64): register weights, FMA-bound ----------------
// Block 256 = 8 warps. Warp w: points pg = w>>1 (8 per group of 32), ch = (w&1)*32 + lane.
// Weights cached in 64 registers per lane; x transposed in smem, broadcast LDS.128.
template<int STAGE>
__global__ __launch_bounds__(256, 2) void k_fconv(const float* __restrict__ in,
                                                  const float* __restrict__ W,
                                                  const float* __restrict__ B) {
    __shared__ float wsmT[64 * 65];       // [c][h] padded
    __shared__ float xT[4 * 64 * 8];      // [pg][c][p]
    __shared__ float fsc[64], fsh[64];
    __shared__ float sstat[128];
    int t = threadIdx.x;
    int warp = t >> 5, lane = t & 31;
    int pg = warp >> 1;
    int ch = (warp & 1) * 32 + lane;

    // stage weights transposed+padded (conflict-free both ways)
    for (int i = t; i < 4096; i += 256) {
        int h = i >> 6, c = i & 63;
        wsmT[c * 65 + h] = W[i];
    }
    if (STAGE == 1 && t < 64) {
        fsc[t] = g_ss[F1_OFF + t];
        fsh[t] = g_ss[F1_OFF + 64 + t];
    }
    __syncthreads();

    float wreg[64];
    #pragma unroll
    for (int c = 0; c < 64; c++) wreg[c] = wsmT[c * 65 + ch];
    float bias = B[ch];

    const float* src = (STAGE == 0) ? in : g_g1;
    float* dst = (STAGE == 0) ? g_g1 : g_g2;

    float ls = 0.f, lss = 0.f;

    for (int grp = blockIdx.x; grp < NG; grp += gridDim.x) {
        int pbase = grp * 32;
        __syncthreads();
        // load 32 points x 64 ch, transpose to xT[pg][c][p]
        #pragma unroll
        for (int q = 0; q < 2; q++) {
            int idx = t + q * 256;           // 0..511
            int p = idx >> 4, c4 = idx & 15;
            float4 v = *(const float4*)&src[(size_t)(pbase + p) * 64 + c4 * 4];
            if (STAGE == 1) {
                int c = c4 * 4;
                v.x = fmaxf(fsc[c + 0] * v.x + fsh[c + 0], 0.f);
                v.y = fmaxf(fsc[c + 1] * v.y + fsh[c + 1], 0.f);
                v.z = fmaxf(fsc[c + 2] * v.z + fsh[c + 2], 0.f);
                v.w = fmaxf(fsc[c + 3] * v.w + fsh[c + 3], 0.f);
            }
            float* xd = &xT[(p >> 3) * 512 + (p & 7)];
            xd[(c4 * 4 + 0) * 8] = v.x;
            xd[(c4 * 4 + 1) * 8] = v.y;
            xd[(c4 * 4 + 2) * 8] = v.z;
            xd[(c4 * 4 + 3) * 8] = v.w;
        }
        __syncthreads();

        float acc[8];
        #pragma unroll
        for (int i = 0; i < 8; i++) acc[i] = bias;
        const float* xp = &xT[pg * 512];
        #pragma unroll
        for (int c = 0; c < 64; c++) {
            float4 xa = *(const float4*)(xp + c * 8);
            float4 xb = *(const float4*)(xp + c * 8 + 4);
            float wv = wreg[c];
            acc[0] += wv * xa.x; acc[1] += wv * xa.y;
            acc[2] += wv * xa.z; acc[3] += wv * xa.w;
            acc[4] += wv * xb.x; acc[5] += wv * xb.y;
            acc[6] += wv * xb.z; acc[7] += wv * xb.w;
        }
        int p0 = pbase + pg * 8;
        #pragma unroll
        for (int i = 0; i < 8; i++) {
            float y = acc[i];
            dst[(size_t)(p0 + i) * 64 + ch] = y;
            float w = (float)g_cnt[p0 + i];
            ls += w * y;
            lss += w * y * y;
        }
    }

    __syncthreads();
    if (t < 128) sstat[t] = 0.f;
    __syncthreads();
    atomicAdd(&sstat[ch], ls);
    atomicAdd(&sstat[64 + ch], lss);
    __syncthreads();
    if (t < 128) atomicAdd(&g_stats[(STAGE == 0 ? F1_OFF : F2_OFF) + t], sstat[t]);
}

// ---------------- w-path layer 1 ----------------
__global__ __launch_bounds__(256, 3) void k_w1(const float* __restrict__ xyz,
                                               const float* __restrict__ cov,
                                               const float* __restrict__ feats,
                                               const int* __restrict__ knn,
                                               const float* __restrict__ ww1,
                                               const float* __restrict__ wb1) {
    __shared__ float wsm[112];
    __shared__ float bsm[8];
    int t = threadIdx.x;
    if (t < 112) wsm[t] = ww1[t];
    if (t < 8)   bsm[t] = wb1[t];
    __syncthreads();
    float ls[8], lss[8];
    #pragma unroll
    for (int o = 0; o < 8; o++) { ls[o] = 0.f; lss[o] = 0.f; }
    for (int i = blockIdx.x * 256 + t; i < NK; i += gridDim.x * 256) {
        int n = i >> 4;
        int j  = knn[i];
        int j0 = knn[n << 4];
        float lx = xyz[j * 3 + 0] - xyz[j0 * 3 + 0];
        float ly = xyz[j * 3 + 1] - xyz[j0 * 3 + 1];
        float lz = xyz[j * 3 + 2] - xyz[j0 * 3 + 2];
        float nax = feats[j * 64 + 3],  nay = feats[j * 64 + 4],  naz = feats[j * 64 + 5];
        float nmx = feats[j0 * 64 + 3], nmy = feats[j0 * 64 + 4], nmz = feats[j0 * 64 + 5];
        float rn = sqrtf(lx * lx + ly * ly + lz * lz);
        float inv = 1.f / fmaxf(rn, 1e-12f);
        float rx = lx * inv, ry = ly * inv, rz = lz * inv;
        float dot = nmx * rx + nmy * ry + nmz * rz;
        float vx = nmx - dot * rx, vy = nmy - dot * ry, vz = nmz - dot * rz;
        float vi = 1.f / fmaxf(sqrtf(vx * vx + vy * vy + vz * vz), 1e-12f);
        vx *= vi; vy *= vi; vz *= vi;
        float wx = ry * vz - rz * vy;
        float wy = rz * vx - rx * vz;
        float wz = rx * vy - ry * vx;
        float wi = 1.f / fmaxf(sqrtf(wx * wx + wy * wy + wz * wz), 1e-12f);
        wx *= wi; wy *= wi; wz *= wi;
        float t1 = nax * nmx + nay * nmy + naz * nmz;
        float t3 = rx * nax + ry * nay + rz * naz;
        float t4 = lx * nmx + ly * nmy + lz * nmz;
        float t6 = nax * vx + nay * vy + naz * vz;
        float t7 = nax * wx + nay * wy + naz * wz;
        float cx = nay * nmz - naz * nmy;
        float cy = naz * nmx - nax * nmz;
        float cz = nax * nmy - nay * nmx;
        float t8 = lx * cx + ly * cy + lz * cz;
        const float* cg = &cov[j * 9];
        float s1 = lx * (cg[0] * lx + cg[1] * ly + cg[2] * lz)
                 + ly * (cg[3] * lx + cg[4] * ly + cg[5] * lz)
                 + lz * (cg[6] * lx + cg[7] * ly + cg[8] * lz);
        const float* c0 = &cov[j0 * 9];
        float s2 = lx * (c0[0] * lx + c0[1] * ly + c0[2] * lz)
                 + ly * (c0[3] * lx + c0[4] * ly + c0[5] * lz)
                 + lz * (c0[6] * lx + c0[7] * ly + c0[8] * lz);
        float win[14] = {lx, ly, lz, t1, dot, t3, t4, t3, t6, t7, t8, rn, s1, s2};
        float ya[8];
        #pragma unroll
        for (int o = 0; o < 8; o++) {
            float y = bsm[o];
            #pragma unroll
            for (int c = 0; c < 14; c++) y += wsm[o * 14 + c] * win[c];
            ya[o] = y;
            ls[o] += y; lss[o] += y * y;
        }
        float4* dst = (float4*)&g_y1w[i * 8];
        dst[0] = make_float4(ya[0], ya[1], ya[2], ya[3]);
        dst[1] = make_float4(ya[4], ya[5], ya[6], ya[7]);
    }
    stats_reduce<8>(ls, lss, W1_OFF);
}

// ---------------- w-path layer 2 ----------------
__global__ __launch_bounds__(256) void k_w2(const float* __restrict__ ww2,
                                            const float* __restrict__ wb2) {
    __shared__ float wsm[64], bsm[8], ssc[8], ssh[8];
    int t = threadIdx.x;
    if (t < 64) wsm[t] = ww2[t];
    if (t < 8) { bsm[t] = wb2[t]; ssc[t] = g_ss[W1_OFF + t]; ssh[t] = g_ss[W1_OFF + 8 + t]; }
    __syncthreads();
    float ls[8], lss[8];
    #pragma unroll
    for (int o = 0; o < 8; o++) { ls[o] = 0.f; lss[o] = 0.f; }
    for (int i = blockIdx.x * 256 + t; i < NK; i += gridDim.x * 256) {
        float a[8];
        float4 a0 = *(const float4*)&g_y1w[i * 8];
        float4 a1 = *(const float4*)&g_y1w[i * 8 + 4];
        a[0] = a0.x; a[1] = a0.y; a[2] = a0.z; a[3] = a0.w;
        a[4] = a1.x; a[5] = a1.y; a[6] = a1.z; a[7] = a1.w;
        #pragma unroll
        for (int c = 0; c < 8; c++) a[c] = fmaxf(ssc[c] * a[c] + ssh[c], 0.f);
        float ya[8];
        #pragma unroll
        for (int o = 0; o < 8; o++) {
            float y = bsm[o];
            #pragma unroll
            for (int c = 0; c < 8; c++) y += wsm[o * 8 + c] * a[c];
            ya[o] = y;
            ls[o] += y; lss[o] += y * y;
        }
        float4* dst = (float4*)&g_y2w[i * 8];
        dst[0] = make_float4(ya[0], ya[1], ya[2], ya[3]);
        dst[1] = make_float4(ya[4], ya[5], ya[6], ya[7]);
    }
    stats_reduce<8>(ls, lss, W2_OFF);
}

// ---------------- w-path layer 3: stats only ----------------
__global__ __launch_bounds__(256) void k_w3s(const float* __restrict__ ww3,
                                             const float* __restrict__ wb3) {
    __shared__ float wsm[128], bsm[16], ssc[8], ssh[8];
    int t = threadIdx.x;
    if (t < 128) wsm[t] = ww3[t];
    if (t < 16)  bsm[t] = wb3[t];
    if (t < 8) { ssc[t] = g_ss[W2_OFF + t]; ssh[t] = g_ss[W2_OFF + 8 + t]; }
    __syncthreads();
    float ls[16], lss[16];
    #pragma unroll
    for (int o = 0; o < 16; o++) { ls[o] = 0.f; lss[o] = 0.f; }
    for (int i = blockIdx.x * 256 + t; i < NK; i += gridDim.x * 256) {
        float a[8];
        float4 a0 = *(const float4*)&g_y2w[i * 8];
        float4 a1 = *(const float4*)&g_y2w[i * 8 + 4];
        a[0] = a0.x; a[1] = a0.y; a[2] = a0.z; a[3] = a0.w;
        a[4] = a1.x; a[5] = a1.y; a[6] = a1.z; a[7] = a1.w;
        #pragma unroll
        for (int c = 0; c < 8; c++) a[c] = fmaxf(ssc[c] * a[c] + ssh[c], 0.f);
        #pragma unroll
        for (int o = 0; o < 16; o++) {
            float y = bsm[o];
            #pragma unroll
            for (int c = 0; c < 8; c++) y += wsm[o * 8 + c] * a[c];
            ls[o] += y; lss[o] += y * y;
        }
    }
    stats_reduce<16>(ls, lss, W3_OFF);
}

// ---------------- finalize BN ----------------
__global__ void k_fin(int off, const float* __restrict__ gamma,
                      const float* __restrict__ beta, int nch, float invc) {
    int c = threadIdx.x;
    if (c < nch) {
        float m = g_stats[off + c] * invc;
        float v = g_stats[off + nch + c] * invc - m * m;
        float s = gamma[c] / sqrtf(v + EPS_BN);
        g_ss[off + c] = s;
        g_ss[off + nch + c] = beta[c] - m * s;
    }
}

// ---------------- fpost = relu(BN2(g_g2)) -> g_g1 ----------------
__global__ void k_post() {
    int i = blockIdx.x * 256 + threadIdx.x;
    if (i < NP * 64) {
        int c = i & 63;
        g_g1[i] = fmaxf(g_ss[F2_OFF + c] * g_g2[i] + g_ss[F2_OFF + 64 + c], 0.f);
    }
}

// ---------------- fp16 mma helpers ----------------
__device__ __forceinline__ void mma_f16(float* c, unsigned a0, unsigned a1,
                                        unsigned a2, unsigned a3,
                                        unsigned b0, unsigned b1) {
    asm volatile("mma.sync.aligned.m16n8k16.row.col.f32.f16.f16.f32 "
                 "{%0,%1,%2,%3}, {%4,%5,%6,%7}, {%8,%9}, {%0,%1,%2,%3};"
                 : "+f"(c[0]), "+f"(c[1]), "+f"(c[2]), "+f"(c[3])
                 : "r"(a0), "r"(a1), "r"(a2), "r"(a3), "r"(b0), "r"(b1));
}

__device__ __forceinline__ void cp16(void* sptr, const void* gptr) {
    unsigned saddr = (unsigned)__cvta_generic_to_shared(sptr);
    asm volatile("cp.async.cg.shared.global [%0], [%1], 16;" :: "r"(saddr), "l"(gptr));
}

__device__ __forceinline__ unsigned packh2(float a, float b) {
    __half2 h = __floats2half2_rn(a, b);
    return *(unsigned*)&h;
}

// ---------------- new = f @ w^T per point; store half2 words, K-permuted ----------------
// Per 16-k group (8 words), storage pos p holds word sigma(p) = {0,4,1,5,2,6,3,7}.
__global__ __launch_bounds__(128) void k_new(const int* __restrict__ knn,
                                             const float* __restrict__ ww3,
                                             const float* __restrict__ wb3) {
    __shared__ float sw[256];
    __shared__ int   sj[16];
    __shared__ float sww3[128], swb3[16], sc3[16], sh3[16], sc2[8], sh2[8];
    int t = threadIdx.x, n = blockIdx.x;
    if (t < 128) sww3[t] = ww3[t];
    if (t < 16) {
        swb3[t] = wb3[t];
        sc3[t] = g_ss[W3_OFF + t];
        sh3[t] = g_ss[W3_OFF + 16 + t];
        sj[t] = knn[n * 16 + t];
    }
    if (t >= 16 && t < 24) {
        int c = t - 16;
        sc2[c] = g_ss[W2_OFF + c];
        sh2[c] = g_ss[W2_OFF + 8 + c];
    }
    __syncthreads();
    if (t < 16) {
        int k = t;
        int base = (n * 16 + k) * 8;
        float a[8];
        float4 a0 = *(const float4*)&g_y2w[base];
        float4 a1 = *(const float4*)&g_y2w[base + 4];
        a[0] = a0.x; a[1] = a0.y; a[2] = a0.z; a[3] = a0.w;
        a[4] = a1.x; a[5] = a1.y; a[6] = a1.z; a[7] = a1.w;
        #pragma unroll
        for (int c = 0; c < 8; c++) a[c] = fmaxf(sc2[c] * a[c] + sh2[c], 0.f);
        #pragma unroll
        for (int m = 0; m < 16; m++) {
            float y = swb3[m];
            #pragma unroll
            for (int c = 0; c < 8; c++) y += sww3[m * 8 + c] * a[c];
            sw[m * 16 + k] = fmaxf(sc3[m] * y + sh3[m], 0.f);
        }
    }
    __syncthreads();
    int h = t >> 1, mb = (t & 1) * 8;
    float fv[16];
    #pragma unroll
    for (int k = 0; k < 16; k++)
        fv[k] = g_g1[sj[k] * 64 + h];   // fpost
    float out[8];
    #pragma unroll
    for (int mm = 0; mm < 8; mm++) {
        int m = mb + mm;
        float acc = 0.f;
        #pragma unroll
        for (int k = 0; k < 16; k++) acc += fv[k] * sw[m * 16 + k];
        out[mm] = acc;
    }
    // K-group = h (words h*8..h*8+7). mb=0 -> words 0..3 at pos {0,2,4,6};
    // mb=8 -> words 4..7 at pos {1,3,5,7}.
    unsigned* dst = &g_newh[(size_t)n * 512 + h * 8 + (t & 1)];
    dst[0] = packh2(out[0], out[1]);
    dst[2] = packh2(out[2], out[3]);
    dst[4] = packh2(out[4], out[5]);
    dst[6] = packh2(out[6], out[7]);
}

// ---------------- prep: lin_w -> half2 words, K-permuted ----------------
__global__ void k_preph(const float* __restrict__ lw) {
    int i = blockIdx.x * 256 + threadIdx.x;   // over 64*512 words
    if (i < 64 * 512) {
        int row = i >> 9, W = i & 511;
        int j = W & 7;
        int pos = ((j & 3) << 1) | (j >> 2);
        unsigned v = packh2(lw[row * 1024 + 2 * W], lw[row * 1024 + 2 * W + 1]);
        g_lwth[row * 512 + (W & ~7) + pos] = v;
    }
}

// ---------------- GEMM: z = new(NPx1024) @ lin_w^T(1024x64), fp16 mma + cp.async ----------------
// K-chunk = 64 halves = 32 words per row. Row stride GP=36 words.
#define GP 36
#define GA (128*GP)
#define GB (64*GP)
#define SMEM_G ((2*GA + 2*GB)*4)

__global__ __launch_bounds__(256, 3) void k_gemm(const float* __restrict__ lb) {
    extern __shared__ unsigned sm[];
    unsigned* As[2] = { sm, sm + GA };
    unsigned* Bs[2] = { sm + 2 * GA, sm + 2 * GA + GB };
    int t = threadIdx.x;
    int rbase = blockIdx.x * 128;
    int lane = t & 31, grp = lane >> 2, qid = lane & 3;
    int m0 = (t >> 5) * 16;

    if (rbase + 128 > NP) {
        for (int i = t; i < 2 * GA; i += 256) sm[i] = 0u;
        __syncthreads();
    }

    float cf[8][4];
    #pragma unroll
    for (int nt = 0; nt < 8; nt++)
        #pragma unroll
        for (int j = 0; j < 4; j++) cf[nt][j] = 0.f;

    auto load = [&](int buf, int s) {
        int kc = s * 32;  // word offset
        #pragma unroll
        for (int r4 = 0; r4 < 4; r4++) {
            int seg = t + r4 * 256;                 // 0..1023
            int row = seg >> 3, w16 = seg & 7;
            if (rbase + row < NP)
                cp16(As[buf] + row * GP + w16 * 4,
                     g_newh + (size_t)(rbase + row) * 512 + kc + w16 * 4);
        }
        #pragma unroll
        for (int r2 = 0; r2 < 2; r2++) {
            int seg = t + r2 * 256;                 // 0..511
            int row = seg >> 3, w16 = seg & 7;
            cp16(Bs[buf] + row * GP + w16 * 4,
                 g_lwth + row * 512 + kc + w16 * 4);
        }
        asm volatile("cp.async.commit_group;");
    };

    load(0, 0);
    int cur = 0;
    for (int s = 0; s < 16; s++) {
        if (s < 15) {
            load(cur ^ 1, s + 1);
            asm volatile("cp.async.wait_group 1;");
        } else {
            asm volatile("cp.async.wait_group 0;");
        }
        __syncthreads();
        unsigned* A = As[cur];
        unsigned* B = Bs[cur];
        #pragma unroll
        for (int ks = 0; ks < 4; ks++) {
            uint2 aLo = *(uint2*)&A[(m0 + grp) * GP + ks * 8 + qid * 2];
            uint2 aHi = *(uint2*)&A[(m0 + grp + 8) * GP + ks * 8 + qid * 2];
            #pragma unroll
            for (int nt = 0; nt < 8; nt++) {
                uint2 b = *(uint2*)&B[(nt * 8 + grp) * GP + ks * 8 + qid * 2];
                mma_f16(cf[nt], aLo.x, aHi.x, aLo.y, aHi.y, b.x, b.y);
            }
        }
        __syncthreads();
        cur ^= 1;
    }

    int r0 = rbase + m0 + grp, r1 = r0 + 8;
    #pragma unroll
    for (int nt = 0; nt < 8; nt++) {
        int c0 = nt * 8 + 2 * qid;
        float b0v = __ldg(&lb[c0]), b1v = __ldg(&lb[c0 + 1]);
        if (r0 < NP) *(float2*)&g_z[r0 * 64 + c0] = make_float2(cf[nt][0] + b0v, cf[nt][1] + b1v);
        if (r1 < NP) *(float2*)&g_z[r1 * 64 + c0] = make_float2(cf[nt][2] + b0v, cf[nt][3] + b1v);
    }
}

// ---------------- stats over z ----------------
__global__ __launch_bounds__(256) void k_zstats() {
    __shared__ float sred[128];
    int t = threadIdx.x;
    if (t < 128) sred[t] = 0.f;
    __syncthreads();
    int cg = (t & 15) * 4;
    float s[4] = {0.f, 0.f, 0.f, 0.f}, ss[4] = {0.f, 0.f, 0.f, 0.f};
    for (int i = blockIdx.x * 256 + t; i < NP * 16; i += gridDim.x * 256) {
        float4 v = *(const float4*)&g_z[i * 4];
        s[0] += v.x; ss[0] += v.x * v.x;
        s[1] += v.y; ss[1] += v.y * v.y;
        s[2] += v.z; ss[2] += v.z * v.z;
        s[3] += v.w; ss[3] += v.w * v.w;
    }
    const unsigned FULL = 0xffffffffu;
    #pragma unroll
    for (int j = 0; j < 4; j++) {
        s[j]  += __shfl_down_sync(FULL, s[j], 16);
        ss[j] += __shfl_down_sync(FULL, ss[j], 16);
    }
    if ((t & 31) < 16) {
        #pragma unroll
        for (int j = 0; j < 4; j++) {
            atomicAdd(&sred[cg + j], s[j]);
            atomicAdd(&sred[64 + cg + j], ss[j]);
        }
    }
    __syncthreads();
    if (t < 128) atomicAdd(&g_stats[Z_OFF + t], sred[t]);
}

// ---------------- final BN + relu -> output ----------------
__global__ void k_out(float* __restrict__ out) {
    int i = blockIdx.x * 256 + threadIdx.x;
    if (i < NP * 64) {
        int c = i & 63;
        out[i] = fmaxf(g_ss[Z_OFF + c] * g_z[i] + g_ss[Z_OFF + 64 + c], 0.f);
    }
}

// ---------------- launch ----------------
extern "C" void kernel_launch(void* const* d_in, const int* in_sizes, int n_in,
                              void* d_out, int out_size) {
    const float* xyz   = (const float*)d_in[0];
    const float* cov   = (const float*)d_in[1];
    const float* feats = (const float*)d_in[2];
    const int*   knn   = (const int*)  d_in[3];
    const float* fw1 = (const float*)d_in[4];
    const float* fb1 = (const float*)d_in[5];
    const float* fg1 = (const float*)d_in[6];
    const float* fbe1 = (const float*)d_in[7];
    const float* fw2 = (const float*)d_in[8];
    const float* fb2 = (const float*)d_in[9];
    const float* fg2 = (const float*)d_in[10];
    const float* fbe2 = (const float*)d_in[11];
    const float* ww1 = (const float*)d_in[12];
    const float* wb1 = (const float*)d_in[13];
    const float* wg1 = (const float*)d_in[14];
    const float* wbe1 = (const float*)d_in[15];
    const float* ww2 = (const float*)d_in[16];
    const float* wb2 = (const float*)d_in[17];
    const float* wg2 = (const float*)d_in[18];
    const float* wbe2 = (const float*)d_in[19];
    const float* ww3 = (const float*)d_in[20];
    const float* wb3 = (const float*)d_in[21];
    const float* wg3 = (const float*)d_in[22];
    const float* wbe3 = (const float*)d_in[23];
    const float* lin_w = (const float*)d_in[24];
    const float* lin_b = (const float*)d_in[25];
    const float* bng = (const float*)d_in[26];
    const float* bnb = (const float*)d_in[27];
    float* out = (float*)d_out;

    const float invNK = 1.f / (float)NK;
    const float invN  = 1.f / (float)NP;

    cudaFuncSetAttribute(k_gemm, cudaFuncAttributeMaxDynamicSharedMemorySize, SMEM_G);

    k_zero<<<(NP + 255) / 256, 256>>>();
    k_cnt<<<(NK + 255) / 256, 256>>>(knn);
    k_preph<<<128, 256>>>(lin_w);

    // stage 1
    k_fconv<0><<<1024, 256>>>(feats, fw1, fb1);
    k_w1<<<2048, 256>>>(xyz, cov, feats, knn, ww1, wb1);
    k_fin<<<1, 64>>>(F1_OFF, fg1, fbe1, 64, invNK);
    k_fin<<<1, 64>>>(W1_OFF, wg1, wbe1, 8, invNK);

    // stage 2
    k_fconv<1><<<1024, 256>>>(nullptr, fw2, fb2);
    k_w2<<<2048, 256>>>(ww2, wb2);
    k_fin<<<1, 64>>>(F2_OFF, fg2, fbe2, 64, invNK);
    k_fin<<<1, 64>>>(W2_OFF, wg2, wbe2, 8, invNK);

    // fpost + stage 3 (w path)
    k_post<<<(NP * 64 + 255) / 256, 256>>>();
    k_w3s<<<2048, 256>>>(ww3, wb3);
    k_fin<<<1, 64>>>(W3_OFF, wg3, wbe3, 16, invNK);

    // einsum + GEMM + final BN
    k_new<<<NP, 128>>>(knn, ww3, wb3);
    k_gemm<<<(NP + 127) / 128, 256, SMEM_G>>>(lin_b);
    k_zstats<<<512, 256>>>();
    k_fin<<<1, 64>>>(Z_OFF, bng, bnb, 64, invN);
    k_out<<<(NP * 64 + 255) / 256, 256>>>(out);
}